// round 8
// baseline (speedup 1.0000x reference)
#include <cuda_runtime.h>
#include <cstdint>

#define L 4096
#define NB 4

// Scratch (no device allocation allowed in kernel_launch)
__device__ float g_rows[NB * L];   // g_rows[c*L + x] = base_table[seq[x]*4 + c]

// ---------------------------------------------------------------------------
// Prep (unchanged from R4): 32 blocks x 128 threads.
// dtype detection per block: 64 odd-word samples within the first 2048
// elements (int64 values 0..3 -> all zero; int32 -> ~surely nonzero).
// All detection reads stay within the 16 KB int32 footprint.
// ---------------------------------------------------------------------------
__global__ void prep_kernel(const int* __restrict__ w,
                            const float* __restrict__ tab) {
    __shared__ int s_nonzero_odd;
    const int tid = threadIdx.x;
    const int b   = blockIdx.x;

    if (tid == 0) s_nonzero_odd = 0;
    __syncthreads();

    if (tid < 64) {
        const int k = b * 64 + tid;            // k in [0, 2048)
        if (w[2 * k + 1] != 0) atomicOr(&s_nonzero_odd, 1);
    }
    __syncthreads();
    const int sh = (s_nonzero_odd == 0) ? 1 : 0;

    const int i = b * 128 + tid;
    const int s = w[i << sh];
    #pragma unroll
    for (int c = 0; c < NB; c++) {
        g_rows[c * L + i] = tab[s * NB + c];
    }
}

// ---------------------------------------------------------------------------
// Fill: 2048 blocks x 256 threads, 64 STG.128/thread, EVERY block writes a
// fully contiguous 256 KB region (16 consecutive output rows).
//
// Blocks [0,1024): channels 4..7 (value = f(column)).
//   b -> (c2 = b>>8, slice = b&255) -> rows [slice*16, slice*16+16) of
//   channel 4+c2. Thread registers its 4 column float4s ONCE (L2-hit), then
//   streams 16 rows x 4 coalesced stores front-to-back. No loads in loop.
//
// Blocks [1024,2048): channels 0..3 (value = f(row)). Unchanged from R2/R4:
//   16 consecutive global rows; per row one broadcast scalar load + 4
//   broadcast float4 stores per thread. Already contiguous per block.
// ---------------------------------------------------------------------------
__global__ void __launch_bounds__(256, 8)
fill_kernel(float4* __restrict__ out) {
    const int tid = threadIdx.x;
    const unsigned b = blockIdx.x;

    if (b < 1024u) {
        const int c2    = b >> 8;              // 0..3 (channel - 4)
        const int slice = b & 255;             // 16-row slice within channel

        const float4* row = (const float4*)&g_rows[c2 << 12];
        const float4 v0 = row[          tid];
        const float4 v1 = row[256     + tid];
        const float4 v2 = row[512     + tid];
        const float4 v3 = row[768     + tid];

        float4* p = out
                  + (((size_t)(4 + c2) << 12) + ((size_t)slice << 4)) * 1024
                  + tid;
        #pragma unroll 4
        for (int r = 0; r < 16; r++) {
            p[0]   = v0;
            p[256] = v1;
            p[512] = v2;
            p[768] = v3;
            p += 1024;                         // next consecutive row
        }
    } else {
        const unsigned row0 = (b - 1024u) << 4;   // 16 rows, global rows 0..16383
        #pragma unroll 1
        for (int r = 0; r < 16; r++) {
            const unsigned row = row0 + r;
            const float s = g_rows[row];          // row == c*4096 + i
            const float4 v = make_float4(s, s, s, s);
            float4* o = out + (size_t)row * 1024 + tid;
            #pragma unroll
            for (int k = 0; k < 4; k++)
                o[k * 256] = v;
        }
    }
}

extern "C" void kernel_launch(void* const* d_in, const int* in_sizes, int n_in,
                              void* d_out, int out_size) {
    const int*   seq        = (const int*)d_in[0];
    const float* base_table = (const float*)d_in[1];

    prep_kernel<<<32, 128>>>(seq, base_table);
    fill_kernel<<<2048, 256>>>((float4*)d_out);
}